// round 6
// baseline (speedup 1.0000x reference)
#include <cuda_runtime.h>
#include <cuda_fp16.h>
#include <cstdint>

#define HDIM     128
#define INDIM    13
#define B_TOTAL  262144
#define TILE_M   128
#define NBT      (B_TOTAL / TILE_M)
#define NTHREADS 512

// packed weights: [512 cols][144 k] fp16, col = nh*256 + wn*64 + gate*16 + jl
__device__ __align__(16) __half g_W[512 * 144];
__device__ float  g_bias[512];
// pre-converted x: [B][16] fp16 (13 real + 3 zero)
__device__ __align__(16) __half g_x16[B_TOTAL * 16];

struct WP { const float *Wx[4], *bx[4], *Wh[4], *bh[4]; };

__global__ void prep_kernel(WP p, const float* __restrict__ x_in) {
    int idx = blockIdx.x * blockDim.x + threadIdx.x;
    if (idx < 512) {
        int r = idx & 255, nh = idx >> 8;
        int wn = r >> 6, gate = (r >> 4) & 3, jl = r & 15;
        int j = nh * 64 + wn * 16 + jl;
        g_bias[idx] = p.bx[gate][j] + p.bh[gate][j];
    }
    if (idx < 512 * 144) {
        int col = idx / 144, k = idx - col * 144;
        int r = col & 255, nh = col >> 8;
        int wn = r >> 6, gate = (r >> 4) & 3, jl = r & 15;
        int j = nh * 64 + wn * 16 + jl;
        float v = 0.f;
        if (k < INDIM)               v = p.Wx[gate][j * INDIM + k];
        else if (k >= 16 && k < 144) v = p.Wh[gate][j * HDIM + (k - 16)];
        g_W[col * 144 + k] = __float2half_rn(v);
    }
    if (idx < B_TOTAL * 16) {
        int r = idx >> 4, c = idx & 15;
        float v = (c < INDIM) ? x_in[(size_t)r * INDIM + c] : 0.f;
        g_x16[idx] = __float2half_rn(v);
    }
}

__device__ __forceinline__ uint32_t smem_u32(const void* p) {
    uint32_t a;
    asm("{ .reg .u64 t; cvta.to.shared.u64 t, %1; cvt.u32.u64 %0, t; }" : "=r"(a) : "l"(p));
    return a;
}
__device__ __forceinline__ float fsig(float x) {
    float t;
    asm("tanh.approx.f32 %0, %1;" : "=f"(t) : "f"(x * 0.5f));
    return fmaf(t, 0.5f, 0.5f);
}
__device__ __forceinline__ float htanh(float x) { return fminf(fmaxf(x, -1.f), 1.f); }

#define CP16(dst, src) \
    asm volatile("cp.async.cg.shared.global [%0], [%1], 16;" :: "r"(dst), "l"(src))
#define CP_COMMIT() asm volatile("cp.async.commit_group;" ::: "memory")
#define CP_WAIT1()  asm volatile("cp.async.wait_group 1;" ::: "memory")

// smem byte offsets (all 16B aligned)
#define SM_B    0u        // weights: 256 x 144 fp16             = 73728
#define SM_AS   73728u    // A (h cols) fp16, pitch 136 halves   = 34816  [hs fp32 p68 aliases]
#define SM_XS   108544u   // x fp16, pitch 16 halves             = 4096
#define SM_H32  112640u   // h fp32 scratch, pitch 132 floats    = 67584
#define SM_CS   180224u   // c fp32 staging, pitch 68 floats     = 34816
#define SMEM_BYTES 215040u

#define APITCH 136
#define CPITCH 68
#define HPITCH 132

__global__ void __launch_bounds__(NTHREADS, 1)
lstm_kernel(const float* __restrict__ h_in, const float* __restrict__ c_in,
            float* __restrict__ out)
{
    extern __shared__ char sm[];
    const uint32_t base = smem_u32(sm);
    __half* Bs  = (__half*)(sm + SM_B);
    __half* As  = (__half*)(sm + SM_AS);
    __half* Xs  = (__half*)(sm + SM_XS);
    float*  h32 = (float*)(sm + SM_H32);
    float*  cs  = (float*)(sm + SM_CS);
    float*  hsf = (float*)(sm + SM_AS);   // hs staging aliases As (after MMA)

    const int tid  = threadIdx.x;
    const int lane = tid & 31;
    const int wid  = tid >> 5;
    const int q    = lane & 3;
    const int gid  = lane >> 2;
    const int wm   = wid >> 2;   // 0..3 (rows wm*32..)
    const int wn   = wid & 3;    // 0..3 (cols wn*64..)

    const int nh     = blockIdx.x & 1;
    const int cidx   = blockIdx.x >> 1;
    const int npairs = gridDim.x >> 1;

    // stage this CTA's weight half once (g_W pitch == Bs pitch == 144)
    {
        const uint4* wsrc = (const uint4*)g_W + nh * 4608;   // FIX: nh offset
        uint4* wdst = (uint4*)Bs;
        #pragma unroll
        for (int it = 0; it < 9; it++) wdst[tid + it * NTHREADS] = wsrc[tid + it * NTHREADS];
    }

    // per-thread bias (column-only), straight from global
    float binit[8][2];
    #pragma unroll
    for (int nt = 0; nt < 8; nt++) {
        binit[nt][0] = g_bias[nh * 256 + wn * 64 + nt * 8 + 2 * q + 0];
        binit[nt][1] = g_bias[nh * 256 + wn * 64 + nt * 8 + 2 * q + 1];
    }

    float* out_h  = out;
    float* out_h2 = out + (size_t)B_TOTAL * HDIM;
    float* out_c  = out + (size_t)2 * B_TOTAL * HDIM;

    // ---- prologue: issue h(t0), x(t0) ----
    {
        const int rb0 = cidx * TILE_M;
        #pragma unroll
        for (int cc = 0; cc < 8; cc++) {
            int id = tid + cc * NTHREADS;           // 0..4095
            int r = id >> 5, k16 = id & 31;
            CP16(base + SM_H32 + r * (HPITCH * 4) + k16 * 16,
                 (const char*)h_in + ((size_t)(rb0 + r) * HDIM + k16 * 4) * 4);
        }
        CP_COMMIT();
        if (tid < 256) {
            int r = tid >> 1, k16 = tid & 1;
            CP16(base + SM_XS + r * 32 + k16 * 16,
                 (const char*)g_x16 + ((size_t)(rb0 + r) * 16 + k16 * 8) * 2);
        }
        CP_COMMIT();
    }

    for (int bt = cidx; bt < NBT; bt += npairs) {
        const int rowbase = bt * TILE_M;
        int btn = bt + npairs; if (btn >= NBT) btn = bt;   // clamp (re-read, harmless)
        const int rbn = btn * TILE_M;

        __syncthreads();                       // B0: store(t-1) done with hs/cs

        // A: issue c(t) -> cs
        #pragma unroll
        for (int cc = 0; cc < 4; cc++) {
            int id = tid + cc * NTHREADS;      // 0..2047
            int r = id >> 4, k16 = id & 15;
            CP16(base + SM_CS + r * (CPITCH * 4) + k16 * 16,
                 (const char*)c_in + ((size_t)(rowbase + r) * HDIM + nh * 64 + k16 * 4) * 4);
        }
        CP_COMMIT();

        CP_WAIT1();                            // B: h(t), x(t) retired; c(t) pending
        __syncthreads();                       // B1: h32/xs visible to all

        // C: convert h32 -> As (fp32 -> fp16)
        {
            int row = tid >> 2, seg = tid & 3;
            const float* hrow = h32 + row * HPITCH + seg * 32;
            __half* arow = As + row * APITCH + seg * 32;
            #pragma unroll
            for (int j4 = 0; j4 < 8; j4++) {
                float4 v = *(const float4*)(hrow + j4 * 4);
                *(__half2*)(arow + j4 * 4)     = __floats2half2_rn(v.x, v.y);
                *(__half2*)(arow + j4 * 4 + 2) = __floats2half2_rn(v.z, v.w);
            }
        }
        __syncthreads();                       // B2: As visible; h32 free

        // D: issue h(t+1) -> h32
        #pragma unroll
        for (int cc = 0; cc < 8; cc++) {
            int id = tid + cc * NTHREADS;
            int r = id >> 5, k16 = id & 31;
            CP16(base + SM_H32 + r * (HPITCH * 4) + k16 * 16,
                 (const char*)h_in + ((size_t)(rbn + r) * HDIM + k16 * 4) * 4);
        }
        CP_COMMIT();

        // F: MMA, warp tile 32x64, K = 144 (ks0 from Xs, ks1..8 from As)
        float acc[2][8][4];
        #pragma unroll
        for (int mt = 0; mt < 2; mt++)
            #pragma unroll
            for (int nt = 0; nt < 8; nt++) {
                acc[mt][nt][0] = binit[nt][0]; acc[mt][nt][1] = binit[nt][1];
                acc[mt][nt][2] = binit[nt][0]; acc[mt][nt][3] = binit[nt][1];
            }
        {
            uint32_t af[2][4];
            #pragma unroll
            for (int mt = 0; mt < 2; mt++) {
                const __half* ap = Xs + (wm * 32 + mt * 16 + gid) * 16 + 2 * q;
                af[mt][0] = *(const uint32_t*)(ap);
                af[mt][1] = *(const uint32_t*)(ap + 8 * 16);
                af[mt][2] = *(const uint32_t*)(ap + 8);
                af[mt][3] = *(const uint32_t*)(ap + 8 * 16 + 8);
            }
            #pragma unroll
            for (int nt = 0; nt < 8; nt++) {
                const __half* bp = Bs + (wn * 64 + nt * 8 + gid) * 144 + 2 * q;
                uint32_t b0 = *(const uint32_t*)(bp);
                uint32_t b1 = *(const uint32_t*)(bp + 8);
                #pragma unroll
                for (int mt = 0; mt < 2; mt++)
                    asm("mma.sync.aligned.m16n8k16.row.col.f32.f16.f16.f32 "
                        "{%0,%1,%2,%3}, {%4,%5,%6,%7}, {%8,%9}, {%0,%1,%2,%3};"
                        : "+f"(acc[mt][nt][0]), "+f"(acc[mt][nt][1]),
                          "+f"(acc[mt][nt][2]), "+f"(acc[mt][nt][3])
                        : "r"(af[mt][0]), "r"(af[mt][1]), "r"(af[mt][2]), "r"(af[mt][3]),
                          "r"(b0), "r"(b1));
            }
        }
        #pragma unroll 1
        for (int ks = 1; ks < 9; ks++) {
            const int kb = (ks - 1) * 16 + 2 * q;
            uint32_t af[2][4];
            #pragma unroll
            for (int mt = 0; mt < 2; mt++) {
                const __half* ap = As + (wm * 32 + mt * 16 + gid) * APITCH + kb;
                af[mt][0] = *(const uint32_t*)(ap);
                af[mt][1] = *(const uint32_t*)(ap + 8 * APITCH);
                af[mt][2] = *(const uint32_t*)(ap + 8);
                af[mt][3] = *(const uint32_t*)(ap + 8 * APITCH + 8);
            }
            #pragma unroll
            for (int nt = 0; nt < 8; nt++) {
                const __half* bp = Bs + (wn * 64 + nt * 8 + gid) * 144 + ks * 16 + 2 * q;
                uint32_t b0 = *(const uint32_t*)(bp);
                uint32_t b1 = *(const uint32_t*)(bp + 8);
                #pragma unroll
                for (int mt = 0; mt < 2; mt++)
                    asm("mma.sync.aligned.m16n8k16.row.col.f32.f16.f16.f32 "
                        "{%0,%1,%2,%3}, {%4,%5,%6,%7}, {%8,%9}, {%0,%1,%2,%3};"
                        : "+f"(acc[mt][nt][0]), "+f"(acc[mt][nt][1]),
                          "+f"(acc[mt][nt][2]), "+f"(acc[mt][nt][3])
                        : "r"(af[mt][0]), "r"(af[mt][1]), "r"(af[mt][2]), "r"(af[mt][3]),
                          "r"(b0), "r"(b1));
            }
        }

        CP_WAIT1();                            // H: c(t) retired; h(t+1) pending
        __syncthreads();                       // B3: cs visible; As free for hs

        // G: issue x(t+1) -> xs
        if (tid < 256) {
            int r = tid >> 1, k16 = tid & 1;
            CP16(base + SM_XS + r * 32 + k16 * 16,
                 (const char*)g_x16 + ((size_t)(rbn + r) * 16 + k16 * 8) * 2);
        }
        CP_COMMIT();

        // I: epilogue (all 4 gates of (row, j) in-thread)
        #pragma unroll
        for (int mt = 0; mt < 2; mt++) {
            #pragma unroll
            for (int b = 0; b < 2; b++) {
                #pragma unroll
                for (int e = 0; e < 2; e++) {
                    const int jloc = wn * 16 + 8 * b + 2 * q + e;
                    #pragma unroll
                    for (int rs = 0; rs < 2; rs++) {
                        const int row = wm * 32 + mt * 16 + gid + 8 * rs;
                        const int ci  = rs * 2 + e;
                        float pi = acc[mt][0 + b][ci];
                        float pf = acc[mt][2 + b][ci];
                        float pg = acc[mt][4 + b][ci];
                        float po = acc[mt][6 + b][ci];
                        float it = fsig(pi), ft = fsig(pf), ot = fsig(po);
                        float gt = htanh(pg);
                        float ct = ft * cs[row * CPITCH + jloc] + it * gt;
                        float ht = ot * htanh(ct);
                        cs[row * CPITCH + jloc]  = ct;
                        hsf[row * CPITCH + jloc] = ht;
                    }
                }
            }
        }
        __syncthreads();                       // B4

        // J: coalesced float4 stores
        #pragma unroll
        for (int it = 0; it < 4; it++) {
            int i = tid + it * NTHREADS;
            int r = i >> 4, p4 = (i & 15) * 4;
            float4 v = *(float4*)(hsf + r * CPITCH + p4);
            float4 w = *(float4*)(cs  + r * CPITCH + p4);
            size_t o = (size_t)(rowbase + r) * HDIM + nh * 64 + p4;
            *(float4*)(out_h + o)  = v;
            *(float4*)(out_h2 + o) = v;
            *(float4*)(out_c + o)  = w;
        }
    }
}

extern "C" void kernel_launch(void* const* d_in, const int* in_sizes, int n_in,
                              void* d_out, int out_size) {
    WP p;
    for (int g = 0; g < 4; g++) {
        p.Wx[g] = (const float*)d_in[3 + 4 * g];
        p.bx[g] = (const float*)d_in[4 + 4 * g];
        p.Wh[g] = (const float*)d_in[5 + 4 * g];
        p.bh[g] = (const float*)d_in[6 + 4 * g];
    }
    prep_kernel<<<(B_TOTAL * 16 + 255) / 256, 256>>>(p, (const float*)d_in[0]);

    int dev = 0, sms = 0;
    cudaGetDevice(&dev);
    cudaDeviceGetAttribute(&sms, cudaDevAttrMultiProcessorCount, dev);
    if (sms <= 0) sms = 148;
    int grid = sms & ~1;
    cudaFuncSetAttribute(lstm_kernel, cudaFuncAttributeMaxDynamicSharedMemorySize, SMEM_BYTES);
    lstm_kernel<<<grid, NTHREADS, SMEM_BYTES>>>(
        (const float*)d_in[1], (const float*)d_in[2], (float*)d_out);
}

// round 7
// speedup vs baseline: 1.3351x; 1.3351x over previous
#include <cuda_runtime.h>
#include <cuda_fp16.h>
#include <cstdint>

#define HDIM     128
#define INDIM    13
#define B_TOTAL  262144
#define TILE_M   128
#define NBT      (B_TOTAL / TILE_M)
#define NTHREADS 512

// packed weights: [512 cols][144 k] fp16, col = nh*256 + wn*64 + gate*16 + jl
__device__ __align__(16) __half g_W[512 * 144];
__device__ float  g_bias[512];

struct WP { const float *Wx[4], *bx[4], *Wh[4], *bh[4]; };

__global__ void prep_kernel(WP p) {
    int idx = blockIdx.x * blockDim.x + threadIdx.x;
    if (idx < 512) {
        int r = idx & 255, nh = idx >> 8;
        int wn = r >> 6, gate = (r >> 4) & 3, jl = r & 15;
        int j = nh * 64 + wn * 16 + jl;
        g_bias[idx] = p.bx[gate][j] + p.bh[gate][j];
    }
    if (idx < 512 * 144) {
        int col = idx / 144, k = idx - col * 144;
        int r = col & 255, nh = col >> 8;
        int wn = r >> 6, gate = (r >> 4) & 3, jl = r & 15;
        int j = nh * 64 + wn * 16 + jl;
        float v = 0.f;
        if (k < INDIM)               v = p.Wx[gate][j * INDIM + k];
        else if (k >= 16 && k < 144) v = p.Wh[gate][j * HDIM + (k - 16)];
        g_W[col * 144 + k] = __float2half_rn(v);
    }
}

__device__ __forceinline__ float fsig(float x) {
    float t;
    asm("tanh.approx.f32 %0, %1;" : "=f"(t) : "f"(x * 0.5f));
    return fmaf(t, 0.5f, 0.5f);
}
__device__ __forceinline__ float htanh(float x) { return fminf(fmaxf(x, -1.f), 1.f); }

// smem: Bs 256x144 fp16 = 73728 | As 128x136 fp16 = 34816 | Xs 128x16 fp16 = 4096
#define SM_B    0u
#define SM_AS   73728u
#define SM_XS   108544u
#define SMEM_BYTES 112640u
#define APITCH  136

__global__ void __launch_bounds__(NTHREADS, 1)
lstm_kernel(const float* __restrict__ x_in, const float* __restrict__ h_in,
            const float* __restrict__ c_in, float* __restrict__ out)
{
    extern __shared__ char sm[];
    __half* Bs = (__half*)(sm + SM_B);
    __half* As = (__half*)(sm + SM_AS);
    __half* Xs = (__half*)(sm + SM_XS);

    const int tid  = threadIdx.x;
    const int lane = tid & 31;
    const int wid  = tid >> 5;
    const int q    = lane & 3;
    const int gid  = lane >> 2;
    const int wm   = wid >> 2;   // 0..3 (rows wm*32..)
    const int wn   = wid & 3;    // 0..3 (cols wn*64..)

    const int nh     = blockIdx.x & 1;
    const int cidx   = blockIdx.x >> 1;
    const int npairs = gridDim.x >> 1;

    // stage this CTA's weight half once
    {
        const uint4* wsrc = (const uint4*)g_W + nh * 4608;
        uint4* wdst = (uint4*)Bs;
        #pragma unroll
        for (int it = 0; it < 9; it++) wdst[tid + it * NTHREADS] = wsrc[tid + it * NTHREADS];
    }
    // zero Xs once (pad cols 13..15 stay zero; data cols rewritten each tile)
    if (tid < 256) ((uint4*)Xs)[tid] = make_uint4(0, 0, 0, 0);

    // per-thread bias (column-only)
    float binit[8][2];
    #pragma unroll
    for (int nt = 0; nt < 8; nt++) {
        binit[nt][0] = g_bias[nh * 256 + wn * 64 + nt * 8 + 2 * q + 0];
        binit[nt][1] = g_bias[nh * 256 + wn * 64 + nt * 8 + 2 * q + 1];
    }

    float* out_h  = out;
    float* out_h2 = out + (size_t)B_TOTAL * HDIM;
    float* out_c  = out + (size_t)2 * B_TOTAL * HDIM;

    const int colbase = nh * 64 + wn * 16 + 2 * q;   // +8b for b=1

    for (int bt = cidx; bt < NBT; bt += npairs) {
        const int rowbase = bt * TILE_M;

        __syncthreads();   // all warps done reading As/Xs of previous tile

        // ---- c preload: direct LDG.64 in fragment layout (consumed at epilogue)
        float2 cv[2][2][2];
        #pragma unroll
        for (int mt = 0; mt < 2; mt++)
            #pragma unroll
            for (int b = 0; b < 2; b++)
                #pragma unroll
                for (int rs = 0; rs < 2; rs++) {
                    int row = wm * 32 + mt * 16 + gid + 8 * rs;
                    cv[mt][b][rs] = *(const float2*)(
                        c_in + (size_t)(rowbase + row) * HDIM + colbase + 8 * b);
                }

        // ---- h: LDG 2x float4 -> fp16 -> STS.128
        #pragma unroll
        for (int it = 0; it < 4; it++) {
            int i = tid + it * NTHREADS;          // 0..2047
            int r = i >> 4, c8 = (i & 15) * 8;
            const float4* hp = (const float4*)(h_in + (size_t)(rowbase + r) * HDIM + c8);
            float4 v0 = hp[0], v1 = hp[1];
            __half2 a0 = __floats2half2_rn(v0.x, v0.y);
            __half2 a1 = __floats2half2_rn(v0.z, v0.w);
            __half2 a2 = __floats2half2_rn(v1.x, v1.y);
            __half2 a3 = __floats2half2_rn(v1.z, v1.w);
            uint4 pk = make_uint4(*(uint32_t*)&a0, *(uint32_t*)&a1,
                                  *(uint32_t*)&a2, *(uint32_t*)&a3);
            *(uint4*)(As + r * APITCH + c8) = pk;
        }
        // ---- x: flat contiguous LDG.128, scatter-convert to Xs [row][16]
        if (tid < 416) {
            float4 xv = ((const float4*)(x_in + (size_t)rowbase * INDIM))[tid];
            float xs4[4] = {xv.x, xv.y, xv.z, xv.w};
            #pragma unroll
            for (int u = 0; u < 4; u++) {
                int f = tid * 4 + u;
                int r = f / 13, c = f - r * 13;
                Xs[r * 16 + c] = __float2half_rn(xs4[u]);
            }
        }
        __syncthreads();   // As/Xs ready

        // ---- MMA: warp tile 32x64, K = 144 (ks0 from Xs, ks1..8 from As)
        float acc[2][8][4];
        #pragma unroll
        for (int mt = 0; mt < 2; mt++)
            #pragma unroll
            for (int nt = 0; nt < 8; nt++) {
                acc[mt][nt][0] = binit[nt][0]; acc[mt][nt][1] = binit[nt][1];
                acc[mt][nt][2] = binit[nt][0]; acc[mt][nt][3] = binit[nt][1];
            }
        {
            uint32_t af[2][4];
            #pragma unroll
            for (int mt = 0; mt < 2; mt++) {
                const __half* ap = Xs + (wm * 32 + mt * 16 + gid) * 16 + 2 * q;
                af[mt][0] = *(const uint32_t*)(ap);
                af[mt][1] = *(const uint32_t*)(ap + 8 * 16);
                af[mt][2] = *(const uint32_t*)(ap + 8);
                af[mt][3] = *(const uint32_t*)(ap + 8 * 16 + 8);
            }
            #pragma unroll
            for (int nt = 0; nt < 8; nt++) {
                const __half* bp = Bs + (wn * 64 + nt * 8 + gid) * 144 + 2 * q;
                uint32_t b0 = *(const uint32_t*)(bp);
                uint32_t b1 = *(const uint32_t*)(bp + 8);
                #pragma unroll
                for (int mt = 0; mt < 2; mt++)
                    asm("mma.sync.aligned.m16n8k16.row.col.f32.f16.f16.f32 "
                        "{%0,%1,%2,%3}, {%4,%5,%6,%7}, {%8,%9}, {%0,%1,%2,%3};"
                        : "+f"(acc[mt][nt][0]), "+f"(acc[mt][nt][1]),
                          "+f"(acc[mt][nt][2]), "+f"(acc[mt][nt][3])
                        : "r"(af[mt][0]), "r"(af[mt][1]), "r"(af[mt][2]), "r"(af[mt][3]),
                          "r"(b0), "r"(b1));
            }
        }
        #pragma unroll 1
        for (int ks = 1; ks < 9; ks++) {
            const int kb = (ks - 1) * 16 + 2 * q;
            uint32_t af[2][4];
            #pragma unroll
            for (int mt = 0; mt < 2; mt++) {
                const __half* ap = As + (wm * 32 + mt * 16 + gid) * APITCH + kb;
                af[mt][0] = *(const uint32_t*)(ap);
                af[mt][1] = *(const uint32_t*)(ap + 8 * APITCH);
                af[mt][2] = *(const uint32_t*)(ap + 8);
                af[mt][3] = *(const uint32_t*)(ap + 8 * APITCH + 8);
            }
            #pragma unroll
            for (int nt = 0; nt < 8; nt++) {
                const __half* bp = Bs + (wn * 64 + nt * 8 + gid) * 144 + ks * 16 + 2 * q;
                uint32_t b0 = *(const uint32_t*)(bp);
                uint32_t b1 = *(const uint32_t*)(bp + 8);
                #pragma unroll
                for (int mt = 0; mt < 2; mt++)
                    asm("mma.sync.aligned.m16n8k16.row.col.f32.f16.f16.f32 "
                        "{%0,%1,%2,%3}, {%4,%5,%6,%7}, {%8,%9}, {%0,%1,%2,%3};"
                        : "+f"(acc[mt][nt][0]), "+f"(acc[mt][nt][1]),
                          "+f"(acc[mt][nt][2]), "+f"(acc[mt][nt][3])
                        : "r"(af[mt][0]), "r"(af[mt][1]), "r"(af[mt][2]), "r"(af[mt][3]),
                          "r"(b0), "r"(b1));
            }
        }

        // ---- epilogue: compute + direct STG.64 (fragment layout = full 32B sectors)
        #pragma unroll
        for (int mt = 0; mt < 2; mt++) {
            #pragma unroll
            for (int b = 0; b < 2; b++) {
                #pragma unroll
                for (int rs = 0; rs < 2; rs++) {
                    const int row = wm * 32 + mt * 16 + gid + 8 * rs;
                    float2 cc = cv[mt][b][rs];
                    float2 hv, cw;
                    {
                        float pi = acc[mt][0 + b][rs * 2 + 0];
                        float pf = acc[mt][2 + b][rs * 2 + 0];
                        float pg = acc[mt][4 + b][rs * 2 + 0];
                        float po = acc[mt][6 + b][rs * 2 + 0];
                        float it = fsig(pi), ft = fsig(pf), ot = fsig(po);
                        float ct = ft * cc.x + it * htanh(pg);
                        hv.x = ot * htanh(ct); cw.x = ct;
                    }
                    {
                        float pi = acc[mt][0 + b][rs * 2 + 1];
                        float pf = acc[mt][2 + b][rs * 2 + 1];
                        float pg = acc[mt][4 + b][rs * 2 + 1];
                        float po = acc[mt][6 + b][rs * 2 + 1];
                        float it = fsig(pi), ft = fsig(pf), ot = fsig(po);
                        float ct = ft * cc.y + it * htanh(pg);
                        hv.y = ot * htanh(ct); cw.y = ct;
                    }
                    size_t o = (size_t)(rowbase + row) * HDIM + colbase + 8 * b;
                    *(float2*)(out_h + o)  = hv;
                    *(float2*)(out_h2 + o) = hv;
                    *(float2*)(out_c + o)  = cw;
                }
            }
        }
    }
}

extern "C" void kernel_launch(void* const* d_in, const int* in_sizes, int n_in,
                              void* d_out, int out_size) {
    WP p;
    for (int g = 0; g < 4; g++) {
        p.Wx[g] = (const float*)d_in[3 + 4 * g];
        p.bx[g] = (const float*)d_in[4 + 4 * g];
        p.Wh[g] = (const float*)d_in[5 + 4 * g];
        p.bh[g] = (const float*)d_in[6 + 4 * g];
    }
    prep_kernel<<<(512 * 144 + 255) / 256, 256>>>(p);

    int dev = 0, sms = 0;
    cudaGetDevice(&dev);
    cudaDeviceGetAttribute(&sms, cudaDevAttrMultiProcessorCount, dev);
    if (sms <= 0) sms = 148;
    int grid = sms & ~1;
    cudaFuncSetAttribute(lstm_kernel, cudaFuncAttributeMaxDynamicSharedMemorySize, SMEM_BYTES);
    lstm_kernel<<<grid, NTHREADS, SMEM_BYTES>>>(
        (const float*)d_in[0], (const float*)d_in[1], (const float*)d_in[2], (float*)d_out);
}

// round 8
// speedup vs baseline: 1.4256x; 1.0678x over previous
#include <cuda_runtime.h>
#include <cuda_fp16.h>
#include <cstdint>

#define HDIM     128
#define INDIM    13
#define B_TOTAL  262144
#define TILE_M   128
#define NBT      (B_TOTAL / TILE_M)
#define NTHREADS 512

// packed weights: [512 cols][144 k] fp16, col = nh*256 + wn*64 + gate*16 + jl
__device__ __align__(16) __half g_W[512 * 144];
__device__ float  g_bias[512];

struct WP { const float *Wx[4], *bx[4], *Wh[4], *bh[4]; };

__global__ void prep_kernel(WP p) {
    int idx = blockIdx.x * blockDim.x + threadIdx.x;
    if (idx < 512) {
        int r = idx & 255, nh = idx >> 8;
        int wn = r >> 6, gate = (r >> 4) & 3, jl = r & 15;
        int j = nh * 64 + wn * 16 + jl;
        g_bias[idx] = p.bx[gate][j] + p.bh[gate][j];
    }
    if (idx < 512 * 144) {
        int col = idx / 144, k = idx - col * 144;
        int r = col & 255, nh = col >> 8;
        int wn = r >> 6, gate = (r >> 4) & 3, jl = r & 15;
        int j = nh * 64 + wn * 16 + jl;
        float v = 0.f;
        if (k < INDIM)               v = p.Wx[gate][j * INDIM + k];
        else if (k >= 16 && k < 144) v = p.Wh[gate][j * HDIM + (k - 16)];
        g_W[col * 144 + k] = __float2half_rn(v);
    }
}

__device__ __forceinline__ float fsig(float x) {
    float t;
    asm("tanh.approx.f32 %0, %1;" : "=f"(t) : "f"(x * 0.5f));
    return fmaf(t, 0.5f, 0.5f);
}
__device__ __forceinline__ float htanh(float x) { return fminf(fmaxf(x, -1.f), 1.f); }

// smem: Bs 256x152 fp16 = 77824 | As 128x136 fp16 = 34816 | Xs 128x24 fp16 = 6144
#define SM_B    0u
#define SM_AS   77824u
#define SM_XS   112640u
#define SMEM_BYTES 118784u
#define APITCH  136
#define BPITCH  152   // 76 words: gid*12 mod 32 -> all banks distinct (conflict-free)
#define XPITCH  24    // 12 words: same property

__global__ void __launch_bounds__(NTHREADS, 1)
lstm_kernel(const float* __restrict__ x_in, const float* __restrict__ h_in,
            const float* __restrict__ c_in, float* __restrict__ out)
{
    extern __shared__ char sm[];
    __half* Bs = (__half*)(sm + SM_B);
    __half* As = (__half*)(sm + SM_AS);
    __half* Xs = (__half*)(sm + SM_XS);

    const int tid  = threadIdx.x;
    const int lane = tid & 31;
    const int wid  = tid >> 5;
    const int q    = lane & 3;
    const int gid  = lane >> 2;
    const int wm   = wid >> 2;   // 0..3 (rows wm*32..)
    const int wn   = wid & 3;    // 0..3 (cols wn*64..)

    const int nh     = blockIdx.x & 1;
    const int cidx   = blockIdx.x >> 1;
    const int npairs = gridDim.x >> 1;

    // stage this CTA's weight half once: src pitch 18 uint4/row -> dst pitch 19 uint4/row
    {
        const uint4* wsrc = (const uint4*)g_W + nh * 4608;
        uint4* wdst = (uint4*)Bs;
        #pragma unroll
        for (int it = 0; it < 9; it++) {
            int i = tid + it * NTHREADS;          // 0..4607
            int r = i / 18, j = i - r * 18;
            wdst[r * 19 + j] = wsrc[i];
        }
    }
    // zero Xs once (pad cols stay zero; data cols rewritten each tile)
    if (tid < 384) ((uint4*)Xs)[tid] = make_uint4(0, 0, 0, 0);

    // per-thread bias (column-only)
    float binit[8][2];
    #pragma unroll
    for (int nt = 0; nt < 8; nt++) {
        binit[nt][0] = g_bias[nh * 256 + wn * 64 + nt * 8 + 2 * q + 0];
        binit[nt][1] = g_bias[nh * 256 + wn * 64 + nt * 8 + 2 * q + 1];
    }

    float* out_h  = out;
    float* out_h2 = out + (size_t)B_TOTAL * HDIM;
    float* out_c  = out + (size_t)2 * B_TOTAL * HDIM;

    const int colbase = nh * 64 + wn * 16 + 2 * q;   // +8b for b=1

    for (int bt = cidx; bt < NBT; bt += npairs) {
        const int rowbase = bt * TILE_M;

        __syncthreads();   // all warps done reading As/Xs of previous tile

        // ---- c preload: direct LDG.64 in fragment layout (consumed at epilogue)
        float2 cv[2][2][2];
        #pragma unroll
        for (int mt = 0; mt < 2; mt++)
            #pragma unroll
            for (int b = 0; b < 2; b++)
                #pragma unroll
                for (int rs = 0; rs < 2; rs++) {
                    int row = wm * 32 + mt * 16 + gid + 8 * rs;
                    cv[mt][b][rs] = *(const float2*)(
                        c_in + (size_t)(rowbase + row) * HDIM + colbase + 8 * b);
                }

        // ---- h: LDG 2x float4 -> fp16 -> STS.128
        #pragma unroll
        for (int it = 0; it < 4; it++) {
            int i = tid + it * NTHREADS;          // 0..2047
            int r = i >> 4, c8 = (i & 15) * 8;
            const float4* hp = (const float4*)(h_in + (size_t)(rowbase + r) * HDIM + c8);
            float4 v0 = hp[0], v1 = hp[1];
            __half2 a0 = __floats2half2_rn(v0.x, v0.y);
            __half2 a1 = __floats2half2_rn(v0.z, v0.w);
            __half2 a2 = __floats2half2_rn(v1.x, v1.y);
            __half2 a3 = __floats2half2_rn(v1.z, v1.w);
            uint4 pk = make_uint4(*(uint32_t*)&a0, *(uint32_t*)&a1,
                                  *(uint32_t*)&a2, *(uint32_t*)&a3);
            *(uint4*)(As + r * APITCH + c8) = pk;
        }
        // ---- x: flat contiguous LDG.128, scatter-convert to Xs [row][XPITCH]
        if (tid < 416) {
            float4 xv = ((const float4*)(x_in + (size_t)rowbase * INDIM))[tid];
            float xs4[4] = {xv.x, xv.y, xv.z, xv.w};
            #pragma unroll
            for (int u = 0; u < 4; u++) {
                int f = tid * 4 + u;
                int r = f / 13, c = f - r * 13;
                Xs[r * XPITCH + c] = __float2half_rn(xs4[u]);
            }
        }
        __syncthreads();   // As/Xs ready

        // ---- MMA: warp tile 32x64, K = 144 (ks0 from Xs, ks1..8 from As)
        float acc[2][8][4];
        #pragma unroll
        for (int mt = 0; mt < 2; mt++)
            #pragma unroll
            for (int nt = 0; nt < 8; nt++) {
                acc[mt][nt][0] = binit[nt][0]; acc[mt][nt][1] = binit[nt][1];
                acc[mt][nt][2] = binit[nt][0]; acc[mt][nt][3] = binit[nt][1];
            }
        {
            uint32_t af[2][4];
            #pragma unroll
            for (int mt = 0; mt < 2; mt++) {
                const __half* ap = Xs + (wm * 32 + mt * 16 + gid) * XPITCH + 2 * q;
                af[mt][0] = *(const uint32_t*)(ap);
                af[mt][1] = *(const uint32_t*)(ap + 8 * XPITCH);
                af[mt][2] = *(const uint32_t*)(ap + 8);
                af[mt][3] = *(const uint32_t*)(ap + 8 * XPITCH + 8);
            }
            #pragma unroll
            for (int nt = 0; nt < 8; nt++) {
                const __half* bp = Bs + (wn * 64 + nt * 8 + gid) * BPITCH + 2 * q;
                uint32_t b0 = *(const uint32_t*)(bp);
                uint32_t b1 = *(const uint32_t*)(bp + 8);
                #pragma unroll
                for (int mt = 0; mt < 2; mt++)
                    asm("mma.sync.aligned.m16n8k16.row.col.f32.f16.f16.f32 "
                        "{%0,%1,%2,%3}, {%4,%5,%6,%7}, {%8,%9}, {%0,%1,%2,%3};"
                        : "+f"(acc[mt][nt][0]), "+f"(acc[mt][nt][1]),
                          "+f"(acc[mt][nt][2]), "+f"(acc[mt][nt][3])
                        : "r"(af[mt][0]), "r"(af[mt][1]), "r"(af[mt][2]), "r"(af[mt][3]),
                          "r"(b0), "r"(b1));
            }
        }
        #pragma unroll 1
        for (int ks = 1; ks < 9; ks++) {
            const int kb = (ks - 1) * 16 + 2 * q;
            uint32_t af[2][4];
            #pragma unroll
            for (int mt = 0; mt < 2; mt++) {
                const __half* ap = As + (wm * 32 + mt * 16 + gid) * APITCH + kb;
                af[mt][0] = *(const uint32_t*)(ap);
                af[mt][1] = *(const uint32_t*)(ap + 8 * APITCH);
                af[mt][2] = *(const uint32_t*)(ap + 8);
                af[mt][3] = *(const uint32_t*)(ap + 8 * APITCH + 8);
            }
            #pragma unroll
            for (int nt = 0; nt < 8; nt++) {
                const __half* bp = Bs + (wn * 64 + nt * 8 + gid) * BPITCH + ks * 16 + 2 * q;
                uint32_t b0 = *(const uint32_t*)(bp);
                uint32_t b1 = *(const uint32_t*)(bp + 8);
                #pragma unroll
                for (int mt = 0; mt < 2; mt++)
                    asm("mma.sync.aligned.m16n8k16.row.col.f32.f16.f16.f32 "
                        "{%0,%1,%2,%3}, {%4,%5,%6,%7}, {%8,%9}, {%0,%1,%2,%3};"
                        : "+f"(acc[mt][nt][0]), "+f"(acc[mt][nt][1]),
                          "+f"(acc[mt][nt][2]), "+f"(acc[mt][nt][3])
                        : "r"(af[mt][0]), "r"(af[mt][1]), "r"(af[mt][2]), "r"(af[mt][3]),
                          "r"(b0), "r"(b1));
            }
        }

        // ---- epilogue: compute + direct STG.64 (fragment layout = full 32B sectors)
        #pragma unroll
        for (int mt = 0; mt < 2; mt++) {
            #pragma unroll
            for (int b = 0; b < 2; b++) {
                #pragma unroll
                for (int rs = 0; rs < 2; rs++) {
                    const int row = wm * 32 + mt * 16 + gid + 8 * rs;
                    float2 cc = cv[mt][b][rs];
                    float2 hv, cw;
                    {
                        float pi = acc[mt][0 + b][rs * 2 + 0];
                        float pf = acc[mt][2 + b][rs * 2 + 0];
                        float pg = acc[mt][4 + b][rs * 2 + 0];
                        float po = acc[mt][6 + b][rs * 2 + 0];
                        float it = fsig(pi), ft = fsig(pf), ot = fsig(po);
                        float ct = ft * cc.x + it * htanh(pg);
                        hv.x = ot * htanh(ct); cw.x = ct;
                    }
                    {
                        float pi = acc[mt][0 + b][rs * 2 + 1];
                        float pf = acc[mt][2 + b][rs * 2 + 1];
                        float pg = acc[mt][4 + b][rs * 2 + 1];
                        float po = acc[mt][6 + b][rs * 2 + 1];
                        float it = fsig(pi), ft = fsig(pf), ot = fsig(po);
                        float ct = ft * cc.y + it * htanh(pg);
                        hv.y = ot * htanh(ct); cw.y = ct;
                    }
                    size_t o = (size_t)(rowbase + row) * HDIM + colbase + 8 * b;
                    *(float2*)(out_h + o)  = hv;
                    *(float2*)(out_h2 + o) = hv;
                    *(float2*)(out_c + o)  = cw;
                }
            }
        }
    }
}

extern "C" void kernel_launch(void* const* d_in, const int* in_sizes, int n_in,
                              void* d_out, int out_size) {
    WP p;
    for (int g = 0; g < 4; g++) {
        p.Wx[g] = (const float*)d_in[3 + 4 * g];
        p.bx[g] = (const float*)d_in[4 + 4 * g];
        p.Wh[g] = (const float*)d_in[5 + 4 * g];
        p.bh[g] = (const float*)d_in[6 + 4 * g];
    }
    prep_kernel<<<(512 * 144 + 255) / 256, 256>>>(p);

    int dev = 0, sms = 0;
    cudaGetDevice(&dev);
    cudaDeviceGetAttribute(&sms, cudaDevAttrMultiProcessorCount, dev);
    if (sms <= 0) sms = 148;
    int grid = sms & ~1;
    cudaFuncSetAttribute(lstm_kernel, cudaFuncAttributeMaxDynamicSharedMemorySize, SMEM_BYTES);
    lstm_kernel<<<grid, NTHREADS, SMEM_BYTES>>>(
        (const float*)d_in[0], (const float*)d_in[1], (const float*)d_in[2], (float*)d_out);
}

// round 9
// speedup vs baseline: 1.5635x; 1.0967x over previous
#include <cuda_runtime.h>
#include <cuda_fp16.h>
#include <cstdint>

#define HDIM     128
#define INDIM    13
#define B_TOTAL  262144
#define TILE_M   64
#define NBT      (B_TOTAL / TILE_M)     // 4096
#define NTHREADS 256

// packed weights: [512 cols][144 k] fp16, col = nh*256 + wn*64 + gate*16 + jl
__device__ __align__(16) __half g_W[512 * 144];
__device__ float  g_bias[512];

struct WP { const float *Wx[4], *bx[4], *Wh[4], *bh[4]; };

__global__ void prep_kernel(WP p) {
    int idx = blockIdx.x * blockDim.x + threadIdx.x;
    if (idx < 512) {
        int r = idx & 255, nh = idx >> 8;
        int wn = r >> 6, gate = (r >> 4) & 3, jl = r & 15;
        int j = nh * 64 + wn * 16 + jl;
        g_bias[idx] = p.bx[gate][j] + p.bh[gate][j];
    }
    if (idx < 512 * 144) {
        int col = idx / 144, k = idx - col * 144;
        int r = col & 255, nh = col >> 8;
        int wn = r >> 6, gate = (r >> 4) & 3, jl = r & 15;
        int j = nh * 64 + wn * 16 + jl;
        float v = 0.f;
        if (k < INDIM)               v = p.Wx[gate][j * INDIM + k];
        else if (k >= 16 && k < 144) v = p.Wh[gate][j * HDIM + (k - 16)];
        g_W[col * 144 + k] = __float2half_rn(v);
    }
}

__device__ __forceinline__ float fsig(float x) {
    float t;
    asm("tanh.approx.f32 %0, %1;" : "=f"(t) : "f"(x * 0.5f));
    return fmaf(t, 0.5f, 0.5f);
}
__device__ __forceinline__ float htanh(float x) { return fminf(fmaxf(x, -1.f), 1.f); }

// smem per CTA: Bs 256x152 fp16 = 77824 | As 64x136 fp16 = 17408 | Xs 64x24 fp16 = 3072
#define SM_B    0u
#define SM_AS   77824u
#define SM_XS   95232u
#define SMEM_BYTES 98304u
#define APITCH  136
#define BPITCH  152   // 76 words: conflict-free fragment rows
#define XPITCH  24    // 12 words: conflict-free

__global__ void __launch_bounds__(NTHREADS, 2)
lstm_kernel(const float* __restrict__ x_in, const float* __restrict__ h_in,
            const float* __restrict__ c_in, float* __restrict__ out)
{
    extern __shared__ char sm[];
    __half* Bs = (__half*)(sm + SM_B);
    __half* As = (__half*)(sm + SM_AS);
    __half* Xs = (__half*)(sm + SM_XS);

    const int tid  = threadIdx.x;
    const int lane = tid & 31;
    const int wid  = tid >> 5;           // 0..7
    const int q    = lane & 3;
    const int gid  = lane >> 2;
    const int wm   = wid >> 2;           // 0..1 (rows wm*32..)
    const int wn   = wid & 3;            // 0..3 (cols wn*64..)

    const int nh     = blockIdx.x & 1;
    const int cidx   = blockIdx.x >> 1;
    const int npairs = gridDim.x >> 1;

    // stage this CTA's weight half once: src pitch 18 uint4/row -> dst pitch 19 uint4/row
    {
        const uint4* wsrc = (const uint4*)g_W + nh * 4608;
        uint4* wdst = (uint4*)Bs;
        #pragma unroll
        for (int it = 0; it < 18; it++) {
            int i = tid + it * NTHREADS;          // 0..4607
            int r = i / 18, j = i - r * 18;
            wdst[r * 19 + j] = wsrc[i];
        }
    }
    // zero Xs once (pad cols stay zero; data cols rewritten each tile)
    if (tid < 192) ((uint4*)Xs)[tid] = make_uint4(0, 0, 0, 0);

    // per-thread bias (column-only)
    float binit[8][2];
    #pragma unroll
    for (int nt = 0; nt < 8; nt++) {
        binit[nt][0] = g_bias[nh * 256 + wn * 64 + nt * 8 + 2 * q + 0];
        binit[nt][1] = g_bias[nh * 256 + wn * 64 + nt * 8 + 2 * q + 1];
    }

    float* out_h  = out;
    float* out_h2 = out + (size_t)B_TOTAL * HDIM;
    float* out_c  = out + (size_t)2 * B_TOTAL * HDIM;

    const int colbase = nh * 64 + wn * 16 + 2 * q;   // +8b for b=1

    for (int bt = cidx; bt < NBT; bt += npairs) {
        const int rowbase = bt * TILE_M;

        __syncthreads();   // all warps done reading As/Xs of previous tile

        // ---- c preload: direct LDG.64 in fragment layout (consumed at epilogue)
        float2 cv[2][2][2];
        #pragma unroll
        for (int mt = 0; mt < 2; mt++)
            #pragma unroll
            for (int b = 0; b < 2; b++)
                #pragma unroll
                for (int rs = 0; rs < 2; rs++) {
                    int row = wm * 32 + mt * 16 + gid + 8 * rs;
                    cv[mt][b][rs] = *(const float2*)(
                        c_in + (size_t)(rowbase + row) * HDIM + colbase + 8 * b);
                }

        // ---- h: LDG 2x float4 -> fp16 -> STS.128 (64 rows x 16 chunks = 1024)
        #pragma unroll
        for (int it = 0; it < 4; it++) {
            int i = tid + it * NTHREADS;          // 0..1023
            int r = i >> 4, c8 = (i & 15) * 8;
            const float4* hp = (const float4*)(h_in + (size_t)(rowbase + r) * HDIM + c8);
            float4 v0 = hp[0], v1 = hp[1];
            __half2 a0 = __floats2half2_rn(v0.x, v0.y);
            __half2 a1 = __floats2half2_rn(v0.z, v0.w);
            __half2 a2 = __floats2half2_rn(v1.x, v1.y);
            __half2 a3 = __floats2half2_rn(v1.z, v1.w);
            uint4 pk = make_uint4(*(uint32_t*)&a0, *(uint32_t*)&a1,
                                  *(uint32_t*)&a2, *(uint32_t*)&a3);
            *(uint4*)(As + r * APITCH + c8) = pk;
        }
        // ---- x: flat contiguous LDG.128 (64*13 = 832 floats = 208 float4)
        if (tid < 208) {
            float4 xv = ((const float4*)(x_in + (size_t)rowbase * INDIM))[tid];
            float xs4[4] = {xv.x, xv.y, xv.z, xv.w};
            #pragma unroll
            for (int u = 0; u < 4; u++) {
                int f = tid * 4 + u;
                int r = f / 13, c = f - r * 13;
                Xs[r * XPITCH + c] = __float2half_rn(xs4[u]);
            }
        }
        __syncthreads();   // As/Xs ready

        // ---- MMA: warp tile 32x64, K = 144 (ks0 from Xs, ks1..8 from As)
        float acc[2][8][4];
        #pragma unroll
        for (int mt = 0; mt < 2; mt++)
            #pragma unroll
            for (int nt = 0; nt < 8; nt++) {
                acc[mt][nt][0] = binit[nt][0]; acc[mt][nt][1] = binit[nt][1];
                acc[mt][nt][2] = binit[nt][0]; acc[mt][nt][3] = binit[nt][1];
            }
        {
            uint32_t af[2][4];
            #pragma unroll
            for (int mt = 0; mt < 2; mt++) {
                const __half* ap = Xs + (wm * 32 + mt * 16 + gid) * XPITCH + 2 * q;
                af[mt][0] = *(const uint32_t*)(ap);
                af[mt][1] = *(const uint32_t*)(ap + 8 * XPITCH);
                af[mt][2] = *(const uint32_t*)(ap + 8);
                af[mt][3] = *(const uint32_t*)(ap + 8 * XPITCH + 8);
            }
            #pragma unroll
            for (int nt = 0; nt < 8; nt++) {
                const __half* bp = Bs + (wn * 64 + nt * 8 + gid) * BPITCH + 2 * q;
                uint32_t b0 = *(const uint32_t*)(bp);
                uint32_t b1 = *(const uint32_t*)(bp + 8);
                #pragma unroll
                for (int mt = 0; mt < 2; mt++)
                    asm("mma.sync.aligned.m16n8k16.row.col.f32.f16.f16.f32 "
                        "{%0,%1,%2,%3}, {%4,%5,%6,%7}, {%8,%9}, {%0,%1,%2,%3};"
                        : "+f"(acc[mt][nt][0]), "+f"(acc[mt][nt][1]),
                          "+f"(acc[mt][nt][2]), "+f"(acc[mt][nt][3])
                        : "r"(af[mt][0]), "r"(af[mt][1]), "r"(af[mt][2]), "r"(af[mt][3]),
                          "r"(b0), "r"(b1));
            }
        }
        #pragma unroll 1
        for (int ks = 1; ks < 9; ks++) {
            const int kb = (ks - 1) * 16 + 2 * q;
            uint32_t af[2][4];
            #pragma unroll
            for (int mt = 0; mt < 2; mt++) {
                const __half* ap = As + (wm * 32 + mt * 16 + gid) * APITCH + kb;
                af[mt][0] = *(const uint32_t*)(ap);
                af[mt][1] = *(const uint32_t*)(ap + 8 * APITCH);
                af[mt][2] = *(const uint32_t*)(ap + 8);
                af[mt][3] = *(const uint32_t*)(ap + 8 * APITCH + 8);
            }
            #pragma unroll
            for (int nt = 0; nt < 8; nt++) {
                const __half* bp = Bs + (wn * 64 + nt * 8 + gid) * BPITCH + ks * 16 + 2 * q;
                uint32_t b0 = *(const uint32_t*)(bp);
                uint32_t b1 = *(const uint32_t*)(bp + 8);
                #pragma unroll
                for (int mt = 0; mt < 2; mt++)
                    asm("mma.sync.aligned.m16n8k16.row.col.f32.f16.f16.f32 "
                        "{%0,%1,%2,%3}, {%4,%5,%6,%7}, {%8,%9}, {%0,%1,%2,%3};"
                        : "+f"(acc[mt][nt][0]), "+f"(acc[mt][nt][1]),
                          "+f"(acc[mt][nt][2]), "+f"(acc[mt][nt][3])
                        : "r"(af[mt][0]), "r"(af[mt][1]), "r"(af[mt][2]), "r"(af[mt][3]),
                          "r"(b0), "r"(b1));
            }
        }

        // ---- epilogue: compute + direct STG.64 (fragment layout = full 32B sectors)
        #pragma unroll
        for (int mt = 0; mt < 2; mt++) {
            #pragma unroll
            for (int b = 0; b < 2; b++) {
                #pragma unroll
                for (int rs = 0; rs < 2; rs++) {
                    const int row = wm * 32 + mt * 16 + gid + 8 * rs;
                    float2 cc = cv[mt][b][rs];
                    float2 hv, cw;
                    {
                        float pi = acc[mt][0 + b][rs * 2 + 0];
                        float pf = acc[mt][2 + b][rs * 2 + 0];
                        float pg = acc[mt][4 + b][rs * 2 + 0];
                        float po = acc[mt][6 + b][rs * 2 + 0];
                        float it = fsig(pi), ft = fsig(pf), ot = fsig(po);
                        float ct = ft * cc.x + it * htanh(pg);
                        hv.x = ot * htanh(ct); cw.x = ct;
                    }
                    {
                        float pi = acc[mt][0 + b][rs * 2 + 1];
                        float pf = acc[mt][2 + b][rs * 2 + 1];
                        float pg = acc[mt][4 + b][rs * 2 + 1];
                        float po = acc[mt][6 + b][rs * 2 + 1];
                        float it = fsig(pi), ft = fsig(pf), ot = fsig(po);
                        float ct = ft * cc.y + it * htanh(pg);
                        hv.y = ot * htanh(ct); cw.y = ct;
                    }
                    size_t o = (size_t)(rowbase + row) * HDIM + colbase + 8 * b;
                    *(float2*)(out_h + o)  = hv;
                    *(float2*)(out_h2 + o) = hv;
                    *(float2*)(out_c + o)  = cw;
                }
            }
        }
    }
}

extern "C" void kernel_launch(void* const* d_in, const int* in_sizes, int n_in,
                              void* d_out, int out_size) {
    WP p;
    for (int g = 0; g < 4; g++) {
        p.Wx[g] = (const float*)d_in[3 + 4 * g];
        p.bx[g] = (const float*)d_in[4 + 4 * g];
        p.Wh[g] = (const float*)d_in[5 + 4 * g];
        p.bh[g] = (const float*)d_in[6 + 4 * g];
    }
    prep_kernel<<<(512 * 144 + 255) / 256, 256>>>(p);

    int dev = 0, sms = 0;
    cudaGetDevice(&dev);
    cudaDeviceGetAttribute(&sms, cudaDevAttrMultiProcessorCount, dev);
    if (sms <= 0) sms = 152;
    int grid = sms * 2;   // 2 CTAs per SM, nh pairs co-resident
    cudaFuncSetAttribute(lstm_kernel, cudaFuncAttributeMaxDynamicSharedMemorySize, SMEM_BYTES);
    lstm_kernel<<<grid, NTHREADS, SMEM_BYTES>>>(
        (const float*)d_in[0], (const float*)d_in[1], (const float*)d_in[2], (float*)d_out);
}

// round 10
// speedup vs baseline: 1.6353x; 1.0459x over previous
#include <cuda_runtime.h>
#include <cuda_fp16.h>
#include <cstdint>

#define HDIM     128
#define INDIM    13
#define B_TOTAL  262144
#define TILE_M   64
#define NBT      (B_TOTAL / TILE_M)     // 4096
#define NTHREADS 256

// packed weights: [512 cols][144 k] fp16, col = nh*256 + wn*64 + gate*16 + jl
__device__ __align__(16) __half g_W[512 * 144];
__device__ float  g_bias[512];

struct WP { const float *Wx[4], *bx[4], *Wh[4], *bh[4]; };

__global__ void prep_kernel(WP p) {
    int idx = blockIdx.x * blockDim.x + threadIdx.x;
    if (idx < 512) {
        int r = idx & 255, nh = idx >> 8;
        int wn = r >> 6, gate = (r >> 4) & 3, jl = r & 15;
        int j = nh * 64 + wn * 16 + jl;
        g_bias[idx] = p.bx[gate][j] + p.bh[gate][j];
    }
    if (idx < 512 * 144) {
        int col = idx / 144, k = idx - col * 144;
        int r = col & 255, nh = col >> 8;
        int wn = r >> 6, gate = (r >> 4) & 3, jl = r & 15;
        int j = nh * 64 + wn * 16 + jl;
        float v = 0.f;
        if (k < INDIM)               v = p.Wx[gate][j * INDIM + k];
        else if (k >= 16 && k < 144) v = p.Wh[gate][j * HDIM + (k - 16)];
        g_W[col * 144 + k] = __float2half_rn(v);
    }
}

__device__ __forceinline__ uint32_t smem_u32(const void* p) {
    uint32_t a;
    asm("{ .reg .u64 t; cvta.to.shared.u64 t, %1; cvt.u32.u64 %0, t; }" : "=r"(a) : "l"(p));
    return a;
}
__device__ __forceinline__ void ldmx4(uint32_t& r0, uint32_t& r1, uint32_t& r2, uint32_t& r3,
                                      uint32_t addr) {
    asm volatile("ldmatrix.sync.aligned.m8n8.x4.shared.b16 {%0,%1,%2,%3}, [%4];"
                 : "=r"(r0), "=r"(r1), "=r"(r2), "=r"(r3) : "r"(addr));
}
__device__ __forceinline__ float fsig(float x) {
    float t;
    asm("tanh.approx.f32 %0, %1;" : "=f"(t) : "f"(x * 0.5f));
    return fmaf(t, 0.5f, 0.5f);
}
__device__ __forceinline__ float htanh(float x) { return fminf(fmaxf(x, -1.f), 1.f); }

// smem per CTA: Bs 256x152 fp16 = 77824 | As 64x136 fp16 = 17408 | Xs 64x24 fp16 = 3072
#define SM_B    0u
#define SM_AS   77824u
#define SM_XS   95232u
#define SMEM_BYTES 98304u
#define APITCH  136   // 68 words: 8-row blocks hit distinct banks
#define BPITCH  152   // 76 words: distinct banks
#define XPITCH  24    // 12 words: distinct banks

__global__ void __launch_bounds__(NTHREADS, 2)
lstm_kernel(const float* __restrict__ x_in, const float* __restrict__ h_in,
            const float* __restrict__ c_in, float* __restrict__ out)
{
    extern __shared__ char sm[];
    __half* Bs = (__half*)(sm + SM_B);
    __half* As = (__half*)(sm + SM_AS);
    __half* Xs = (__half*)(sm + SM_XS);

    const int tid  = threadIdx.x;
    const int lane = tid & 31;
    const int wid  = tid >> 5;           // 0..7
    const int q    = lane & 3;
    const int gid  = lane >> 2;
    const int wm   = wid >> 2;           // 0..1 (rows wm*32..)
    const int wn   = wid & 3;            // 0..3 (cols wn*64..)

    const int nh     = blockIdx.x & 1;
    const int cidx   = blockIdx.x >> 1;
    const int npairs = gridDim.x >> 1;

    // stage this CTA's weight half once: src pitch 18 uint4/row -> dst pitch 19 uint4/row
    {
        const uint4* wsrc = (const uint4*)g_W + nh * 4608;
        uint4* wdst = (uint4*)Bs;
        #pragma unroll
        for (int it = 0; it < 18; it++) {
            int i = tid + it * NTHREADS;          // 0..4607
            int r = i / 18, j = i - r * 18;
            wdst[r * 19 + j] = wsrc[i];
        }
    }
    // zero Xs once (pad cols stay zero; data cols rewritten each tile)
    if (tid < 192) ((uint4*)Xs)[tid] = make_uint4(0, 0, 0, 0);

    // ldmatrix lane base addresses (constant across tiles)
    // A (and X): lane l -> row (l&15) of warp's 32-row block + k-half (l>>4)
    const uint32_t adA = smem_u32(As) +
        (uint32_t)(((wm * 32 + (lane & 15)) * APITCH + (lane >> 4) * 8) * 2);
    const uint32_t adX = smem_u32(Xs) +
        (uint32_t)(((wm * 32 + (lane & 15)) * XPITCH + (lane >> 4) * 8) * 2);
    // B: lane l -> col (pair-nt (l>>4), row l&7), k-half ((l>>3)&1)
    const uint32_t adB = smem_u32(Bs) +
        (uint32_t)(((wn * 64 + (lane >> 4) * 8 + (lane & 7)) * BPITCH
                    + ((lane >> 3) & 1) * 8) * 2);

    // per-thread bias (column-only)
    float binit[8][2];
    #pragma unroll
    for (int nt = 0; nt < 8; nt++) {
        binit[nt][0] = g_bias[nh * 256 + wn * 64 + nt * 8 + 2 * q + 0];
        binit[nt][1] = g_bias[nh * 256 + wn * 64 + nt * 8 + 2 * q + 1];
    }

    float* out_h  = out;
    float* out_h2 = out + (size_t)B_TOTAL * HDIM;
    float* out_c  = out + (size_t)2 * B_TOTAL * HDIM;

    const int colbase = nh * 64 + wn * 16 + 2 * q;   // +8b for b=1

    for (int bt = cidx; bt < NBT; bt += npairs) {
        const int rowbase = bt * TILE_M;

        __syncthreads();   // all warps done reading As/Xs of previous tile

        // ---- c preload: direct LDG.64 in fragment layout (consumed at epilogue)
        float2 cv[2][2][2];
        #pragma unroll
        for (int mt = 0; mt < 2; mt++)
            #pragma unroll
            for (int b = 0; b < 2; b++)
                #pragma unroll
                for (int rs = 0; rs < 2; rs++) {
                    int row = wm * 32 + mt * 16 + gid + 8 * rs;
                    cv[mt][b][rs] = *(const float2*)(
                        c_in + (size_t)(rowbase + row) * HDIM + colbase + 8 * b);
                }

        // ---- h: LDG 2x float4 -> fp16 -> STS.128 (64 rows x 16 chunks = 1024)
        #pragma unroll
        for (int it = 0; it < 4; it++) {
            int i = tid + it * NTHREADS;          // 0..1023
            int r = i >> 4, c8 = (i & 15) * 8;
            const float4* hp = (const float4*)(h_in + (size_t)(rowbase + r) * HDIM + c8);
            float4 v0 = hp[0], v1 = hp[1];
            __half2 a0 = __floats2half2_rn(v0.x, v0.y);
            __half2 a1 = __floats2half2_rn(v0.z, v0.w);
            __half2 a2 = __floats2half2_rn(v1.x, v1.y);
            __half2 a3 = __floats2half2_rn(v1.z, v1.w);
            uint4 pk = make_uint4(*(uint32_t*)&a0, *(uint32_t*)&a1,
                                  *(uint32_t*)&a2, *(uint32_t*)&a3);
            *(uint4*)(As + r * APITCH + c8) = pk;
        }
        // ---- x: flat contiguous LDG.128 (64*13 = 832 floats = 208 float4)
        if (tid < 208) {
            float4 xv = ((const float4*)(x_in + (size_t)rowbase * INDIM))[tid];
            float xs4[4] = {xv.x, xv.y, xv.z, xv.w};
            #pragma unroll
            for (int u = 0; u < 4; u++) {
                int f = tid * 4 + u;
                int r = f / 13, c = f - r * 13;
                Xs[r * XPITCH + c] = __float2half_rn(xs4[u]);
            }
        }
        __syncthreads();   // As/Xs ready

        // ---- MMA: warp tile 32x64, K = 144 (ks0 from Xs, ks1..8 from As)
        float acc[2][8][4];
        #pragma unroll
        for (int mt = 0; mt < 2; mt++)
            #pragma unroll
            for (int nt = 0; nt < 8; nt++) {
                acc[mt][nt][0] = binit[nt][0]; acc[mt][nt][1] = binit[nt][1];
                acc[mt][nt][2] = binit[nt][0]; acc[mt][nt][3] = binit[nt][1];
            }

        // ks = 0: A from Xs
        {
            uint32_t af[2][4], bf[8][2];
            ldmx4(af[0][0], af[0][1], af[0][2], af[0][3], adX);
            ldmx4(af[1][0], af[1][1], af[1][2], af[1][3], adX + 16 * XPITCH * 2);
            #pragma unroll
            for (int p = 0; p < 4; p++)
                ldmx4(bf[2*p][0], bf[2*p][1], bf[2*p+1][0], bf[2*p+1][1],
                      adB + p * (16 * BPITCH * 2));
            #pragma unroll
            for (int nt = 0; nt < 8; nt++)
                #pragma unroll
                for (int mt = 0; mt < 2; mt++)
                    asm("mma.sync.aligned.m16n8k16.row.col.f32.f16.f16.f32 "
                        "{%0,%1,%2,%3}, {%4,%5,%6,%7}, {%8,%9}, {%0,%1,%2,%3};"
                        : "+f"(acc[mt][nt][0]), "+f"(acc[mt][nt][1]),
                          "+f"(acc[mt][nt][2]), "+f"(acc[mt][nt][3])
                        : "r"(af[mt][0]), "r"(af[mt][1]), "r"(af[mt][2]), "r"(af[mt][3]),
                          "r"(bf[nt][0]), "r"(bf[nt][1]));
        }
        // ks = 1..8: A from As
        #pragma unroll 1
        for (int ks = 1; ks < 9; ks++) {
            uint32_t af[2][4], bf[8][2];
            uint32_t a0 = adA + (uint32_t)(ks - 1) * 32;
            ldmx4(af[0][0], af[0][1], af[0][2], af[0][3], a0);
            ldmx4(af[1][0], af[1][1], af[1][2], af[1][3], a0 + 16 * APITCH * 2);
            uint32_t b0a = adB + (uint32_t)ks * 32;
            #pragma unroll
            for (int p = 0; p < 4; p++)
                ldmx4(bf[2*p][0], bf[2*p][1], bf[2*p+1][0], bf[2*p+1][1],
                      b0a + p * (16 * BPITCH * 2));
            #pragma unroll
            for (int nt = 0; nt < 8; nt++)
                #pragma unroll
                for (int mt = 0; mt < 2; mt++)
                    asm("mma.sync.aligned.m16n8k16.row.col.f32.f16.f16.f32 "
                        "{%0,%1,%2,%3}, {%4,%5,%6,%7}, {%8,%9}, {%0,%1,%2,%3};"
                        : "+f"(acc[mt][nt][0]), "+f"(acc[mt][nt][1]),
                          "+f"(acc[mt][nt][2]), "+f"(acc[mt][nt][3])
                        : "r"(af[mt][0]), "r"(af[mt][1]), "r"(af[mt][2]), "r"(af[mt][3]),
                          "r"(bf[nt][0]), "r"(bf[nt][1]));
        }

        // ---- epilogue: compute + direct STG.64 (fragment layout = full 32B sectors)
        #pragma unroll
        for (int mt = 0; mt < 2; mt++) {
            #pragma unroll
            for (int b = 0; b < 2; b++) {
                #pragma unroll
                for (int rs = 0; rs < 2; rs++) {
                    const int row = wm * 32 + mt * 16 + gid + 8 * rs;
                    float2 cc = cv[mt][b][rs];
                    float2 hv, cw;
                    {
                        float pi = acc[mt][0 + b][rs * 2 + 0];
                        float pf = acc[mt][2 + b][rs * 2 + 0];
                        float pg = acc[mt][4 + b][rs * 2 + 0];
                        float po = acc[mt][6 + b][rs * 2 + 0];
                        float it = fsig(pi), ft = fsig(pf), ot = fsig(po);
                        float ct = ft * cc.x + it * htanh(pg);
                        hv.x = ot * htanh(ct); cw.x = ct;
                    }
                    {
                        float pi = acc[mt][0 + b][rs * 2 + 1];
                        float pf = acc[mt][2 + b][rs * 2 + 1];
                        float pg = acc[mt][4 + b][rs * 2 + 1];
                        float po = acc[mt][6 + b][rs * 2 + 1];
                        float it = fsig(pi), ft = fsig(pf), ot = fsig(po);
                        float ct = ft * cc.y + it * htanh(pg);
                        hv.y = ot * htanh(ct); cw.y = ct;
                    }
                    size_t o = (size_t)(rowbase + row) * HDIM + colbase + 8 * b;
                    *(float2*)(out_h + o)  = hv;
                    *(float2*)(out_h2 + o) = hv;
                    *(float2*)(out_c + o)  = cw;
                }
            }
        }
    }
}

extern "C" void kernel_launch(void* const* d_in, const int* in_sizes, int n_in,
                              void* d_out, int out_size) {
    WP p;
    for (int g = 0; g < 4; g++) {
        p.Wx[g] = (const float*)d_in[3 + 4 * g];
        p.bx[g] = (const float*)d_in[4 + 4 * g];
        p.Wh[g] = (const float*)d_in[5 + 4 * g];
        p.bh[g] = (const float*)d_in[6 + 4 * g];
    }
    prep_kernel<<<(512 * 144 + 255) / 256, 256>>>(p);

    int dev = 0, sms = 0;
    cudaGetDevice(&dev);
    cudaDeviceGetAttribute(&sms, cudaDevAttrMultiProcessorCount, dev);
    if (sms <= 0) sms = 152;
    int grid = sms * 2;   // 2 CTAs per SM, nh pairs co-resident
    cudaFuncSetAttribute(lstm_kernel, cudaFuncAttributeMaxDynamicSharedMemorySize, SMEM_BYTES);
    lstm_kernel<<<grid, NTHREADS, SMEM_BYTES>>>(
        (const float*)d_in[0], (const float*)d_in[1], (const float*)d_in[2], (float*)d_out);
}

// round 11
// speedup vs baseline: 1.7586x; 1.0754x over previous
#include <cuda_runtime.h>
#include <cuda_fp16.h>
#include <cstdint>

#define HDIM     128
#define INDIM    13
#define B_TOTAL  262144
#define TILE_M   64
#define NBT      (B_TOTAL / TILE_M)     // 4096
#define NTHREADS 256

// packed weights fp16: storage col = nh*256 + wn*64 + gate*16 + p,
// where position p = 8b + 2q + e carries OUTPUT column j = 4q + 2b + e
// (within the 16-wide j block). This makes each thread's mma fragment hold
// 4 consecutive output columns -> float4 LDG/STG in the epilogue.
__device__ __align__(16) __half g_W[512 * 144];
__device__ float  g_bias[512];

struct WP { const float *Wx[4], *bx[4], *Wh[4], *bh[4]; };

__global__ void prep_kernel(WP p) {
    int idx = blockIdx.x * blockDim.x + threadIdx.x;
    if (idx < 512) {
        int r = idx & 255, nh = idx >> 8;
        int wn = r >> 6, gate = (r >> 4) & 3, pp = r & 15;
        int jl = 4 * ((pp >> 1) & 3) + 2 * (pp >> 3) + (pp & 1);  // permuted
        int j = nh * 64 + wn * 16 + jl;
        g_bias[idx] = p.bx[gate][j] + p.bh[gate][j];
    }
    if (idx < 512 * 144) {
        int col = idx / 144, k = idx - col * 144;
        int r = col & 255, nh = col >> 8;
        int wn = r >> 6, gate = (r >> 4) & 3, pp = r & 15;
        int jl = 4 * ((pp >> 1) & 3) + 2 * (pp >> 3) + (pp & 1);  // permuted
        int j = nh * 64 + wn * 16 + jl;
        float v = 0.f;
        if (k < INDIM)               v = p.Wx[gate][j * INDIM + k];
        else if (k >= 16 && k < 144) v = p.Wh[gate][j * HDIM + (k - 16)];
        g_W[col * 144 + k] = __float2half_rn(v);
    }
}

__device__ __forceinline__ uint32_t smem_u32(const void* p) {
    uint32_t a;
    asm("{ .reg .u64 t; cvta.to.shared.u64 t, %1; cvt.u32.u64 %0, t; }" : "=r"(a) : "l"(p));
    return a;
}
__device__ __forceinline__ void ldmx4(uint32_t& r0, uint32_t& r1, uint32_t& r2, uint32_t& r3,
                                      uint32_t addr) {
    asm volatile("ldmatrix.sync.aligned.m8n8.x4.shared.b16 {%0,%1,%2,%3}, [%4];"
                 : "=r"(r0), "=r"(r1), "=r"(r2), "=r"(r3) : "r"(addr));
}
__device__ __forceinline__ float fsig(float x) {
    float t;
    asm("tanh.approx.f32 %0, %1;" : "=f"(t) : "f"(x * 0.5f));
    return fmaf(t, 0.5f, 0.5f);
}
__device__ __forceinline__ float htanh(float x) { return fminf(fmaxf(x, -1.f), 1.f); }

// smem per CTA: Bs 256x152 fp16 = 77824 | As 64x136 fp16 = 17408 | Xs 64x24 fp16 = 3072
#define SM_B    0u
#define SM_AS   77824u
#define SM_XS   95232u
#define SMEM_BYTES 98304u
#define APITCH  136
#define BPITCH  152
#define XPITCH  24

__global__ void __launch_bounds__(NTHREADS, 2)
lstm_kernel(const float* __restrict__ x_in, const float* __restrict__ h_in,
            const float* __restrict__ c_in, float* __restrict__ out)
{
    extern __shared__ char sm[];
    __half* Bs = (__half*)(sm + SM_B);
    __half* As = (__half*)(sm + SM_AS);
    __half* Xs = (__half*)(sm + SM_XS);

    const int tid  = threadIdx.x;
    const int lane = tid & 31;
    const int wid  = tid >> 5;           // 0..7
    const int q    = lane & 3;
    const int gid  = lane >> 2;
    const int wm   = wid >> 2;           // 0..1 (rows wm*32..)
    const int wn   = wid & 3;            // 0..3 (cols wn*64..)

    const int nh     = blockIdx.x & 1;
    const int cidx   = blockIdx.x >> 1;
    const int npairs = gridDim.x >> 1;

    // stage this CTA's weight half once: src pitch 18 uint4/row -> dst pitch 19 uint4/row
    {
        const uint4* wsrc = (const uint4*)g_W + nh * 4608;
        uint4* wdst = (uint4*)Bs;
        #pragma unroll
        for (int it = 0; it < 18; it++) {
            int i = tid + it * NTHREADS;          // 0..4607
            int r = i / 18, j = i - r * 18;
            wdst[r * 19 + j] = wsrc[i];
        }
    }
    if (tid < 192) ((uint4*)Xs)[tid] = make_uint4(0, 0, 0, 0);

    // ldmatrix lane base addresses (constant across tiles)
    const uint32_t adA = smem_u32(As) +
        (uint32_t)(((wm * 32 + (lane & 15)) * APITCH + (lane >> 4) * 8) * 2);
    const uint32_t adX = smem_u32(Xs) +
        (uint32_t)(((wm * 32 + (lane & 15)) * XPITCH + (lane >> 4) * 8) * 2);
    const uint32_t adB = smem_u32(Bs) +
        (uint32_t)(((wn * 64 + (lane >> 4) * 8 + (lane & 7)) * BPITCH
                    + ((lane >> 3) & 1) * 8) * 2);

    // per-thread bias (column-only, storage order)
    float binit[8][2];
    #pragma unroll
    for (int nt = 0; nt < 8; nt++) {
        binit[nt][0] = g_bias[nh * 256 + wn * 64 + nt * 8 + 2 * q + 0];
        binit[nt][1] = g_bias[nh * 256 + wn * 64 + nt * 8 + 2 * q + 1];
    }

    float* out_h  = out;
    float* out_h2 = out + (size_t)B_TOTAL * HDIM;
    float* out_c  = out + (size_t)2 * B_TOTAL * HDIM;

    // output column base: 4 consecutive columns per thread
    const int colbase4 = nh * 64 + wn * 16 + 4 * q;

    for (int bt = cidx; bt < NBT; bt += npairs) {
        const int rowbase = bt * TILE_M;

        __syncthreads();   // all warps done reading As/Xs of previous tile

        // ---- c preload: LDG.128 (4 consecutive output cols per thread)
        float4 cv[2][2];
        #pragma unroll
        for (int mt = 0; mt < 2; mt++)
            #pragma unroll
            for (int rs = 0; rs < 2; rs++) {
                int row = wm * 32 + mt * 16 + gid + 8 * rs;
                cv[mt][rs] = *(const float4*)(
                    c_in + (size_t)(rowbase + row) * HDIM + colbase4);
            }

        // ---- h: LDG 2x float4 -> fp16 -> STS.128 (64 rows x 16 chunks = 1024)
        #pragma unroll
        for (int it = 0; it < 4; it++) {
            int i = tid + it * NTHREADS;          // 0..1023
            int r = i >> 4, c8 = (i & 15) * 8;
            const float4* hp = (const float4*)(h_in + (size_t)(rowbase + r) * HDIM + c8);
            float4 v0 = hp[0], v1 = hp[1];
            __half2 a0 = __floats2half2_rn(v0.x, v0.y);
            __half2 a1 = __floats2half2_rn(v0.z, v0.w);
            __half2 a2 = __floats2half2_rn(v1.x, v1.y);
            __half2 a3 = __floats2half2_rn(v1.z, v1.w);
            uint4 pk = make_uint4(*(uint32_t*)&a0, *(uint32_t*)&a1,
                                  *(uint32_t*)&a2, *(uint32_t*)&a3);
            *(uint4*)(As + r * APITCH + c8) = pk;
        }
        // ---- x: flat contiguous LDG.128 (64*13 = 832 floats = 208 float4)
        if (tid < 208) {
            float4 xv = ((const float4*)(x_in + (size_t)rowbase * INDIM))[tid];
            float xs4[4] = {xv.x, xv.y, xv.z, xv.w};
            #pragma unroll
            for (int u = 0; u < 4; u++) {
                int f = tid * 4 + u;
                int r = f / 13, c = f - r * 13;
                Xs[r * XPITCH + c] = __float2half_rn(xs4[u]);
            }
        }
        __syncthreads();   // As/Xs ready

        // ---- MMA: warp tile 32x64, K = 144 (ks0 from Xs, ks1..8 from As)
        float acc[2][8][4];
        #pragma unroll
        for (int mt = 0; mt < 2; mt++)
            #pragma unroll
            for (int nt = 0; nt < 8; nt++) {
                acc[mt][nt][0] = binit[nt][0]; acc[mt][nt][1] = binit[nt][1];
                acc[mt][nt][2] = binit[nt][0]; acc[mt][nt][3] = binit[nt][1];
            }

        // ks = 0: A from Xs
        {
            uint32_t af[2][4], bf[8][2];
            ldmx4(af[0][0], af[0][1], af[0][2], af[0][3], adX);
            ldmx4(af[1][0], af[1][1], af[1][2], af[1][3], adX + 16 * XPITCH * 2);
            #pragma unroll
            for (int p = 0; p < 4; p++)
                ldmx4(bf[2*p][0], bf[2*p][1], bf[2*p+1][0], bf[2*p+1][1],
                      adB + p * (16 * BPITCH * 2));
            #pragma unroll
            for (int nt = 0; nt < 8; nt++)
                #pragma unroll
                for (int mt = 0; mt < 2; mt++)
                    asm("mma.sync.aligned.m16n8k16.row.col.f32.f16.f16.f32 "
                        "{%0,%1,%2,%3}, {%4,%5,%6,%7}, {%8,%9}, {%0,%1,%2,%3};"
                        : "+f"(acc[mt][nt][0]), "+f"(acc[mt][nt][1]),
                          "+f"(acc[mt][nt][2]), "+f"(acc[mt][nt][3])
                        : "r"(af[mt][0]), "r"(af[mt][1]), "r"(af[mt][2]), "r"(af[mt][3]),
                          "r"(bf[nt][0]), "r"(bf[nt][1]));
        }
        // ks = 1..8: A from As
        #pragma unroll 1
        for (int ks = 1; ks < 9; ks++) {
            uint32_t af[2][4], bf[8][2];
            uint32_t a0 = adA + (uint32_t)(ks - 1) * 32;
            ldmx4(af[0][0], af[0][1], af[0][2], af[0][3], a0);
            ldmx4(af[1][0], af[1][1], af[1][2], af[1][3], a0 + 16 * APITCH * 2);
            uint32_t b0a = adB + (uint32_t)ks * 32;
            #pragma unroll
            for (int p = 0; p < 4; p++)
                ldmx4(bf[2*p][0], bf[2*p][1], bf[2*p+1][0], bf[2*p+1][1],
                      b0a + p * (16 * BPITCH * 2));
            #pragma unroll
            for (int nt = 0; nt < 8; nt++)
                #pragma unroll
                for (int mt = 0; mt < 2; mt++)
                    asm("mma.sync.aligned.m16n8k16.row.col.f32.f16.f16.f32 "
                        "{%0,%1,%2,%3}, {%4,%5,%6,%7}, {%8,%9}, {%0,%1,%2,%3};"
                        : "+f"(acc[mt][nt][0]), "+f"(acc[mt][nt][1]),
                          "+f"(acc[mt][nt][2]), "+f"(acc[mt][nt][3])
                        : "r"(af[mt][0]), "r"(af[mt][1]), "r"(af[mt][2]), "r"(af[mt][3]),
                          "r"(bf[nt][0]), "r"(bf[nt][1]));
        }

        // ---- epilogue: 4 consecutive output cols per thread -> STG.128
        // acc[mt][gate*2+b][rs*2+e] is output column colbase4 + 2b + e
        #pragma unroll
        for (int mt = 0; mt < 2; mt++) {
            #pragma unroll
            for (int rs = 0; rs < 2; rs++) {
                const int row = wm * 32 + mt * 16 + gid + 8 * rs;
                float4 cc = cv[mt][rs];
                float cin[4] = {cc.x, cc.y, cc.z, cc.w};
                float hv[4], cw[4];
                #pragma unroll
                for (int b = 0; b < 2; b++)
                    #pragma unroll
                    for (int e = 0; e < 2; e++) {
                        const int s  = 2 * b + e;
                        const int ci = rs * 2 + e;
                        float pi = acc[mt][0 + b][ci];
                        float pf = acc[mt][2 + b][ci];
                        float pg = acc[mt][4 + b][ci];
                        float po = acc[mt][6 + b][ci];
                        float it = fsig(pi), ft = fsig(pf), ot = fsig(po);
                        float ct = ft * cin[s] + it * htanh(pg);
                        hv[s] = ot * htanh(ct);
                        cw[s] = ct;
                    }
                float4 hq = make_float4(hv[0], hv[1], hv[2], hv[3]);
                float4 cq = make_float4(cw[0], cw[1], cw[2], cw[3]);
                size_t o = (size_t)(rowbase + row) * HDIM + colbase4;
                *(float4*)(out_h + o)  = hq;
                *(float4*)(out_h2 + o) = hq;
                *(float4*)(out_c + o)  = cq;
            }
        }
    }
}

extern "C" void kernel_launch(void* const* d_in, const int* in_sizes, int n_in,
                              void* d_out, int out_size) {
    WP p;
    for (int g = 0; g < 4; g++) {
        p.Wx[g] = (const float*)d_in[3 + 4 * g];
        p.bx[g] = (const float*)d_in[4 + 4 * g];
        p.Wh[g] = (const float*)d_in[5 + 4 * g];
        p.bh[g] = (const float*)d_in[6 + 4 * g];
    }
    prep_kernel<<<(512 * 144 + 255) / 256, 256>>>(p);

    int dev = 0, sms = 0;
    cudaGetDevice(&dev);
    cudaDeviceGetAttribute(&sms, cudaDevAttrMultiProcessorCount, dev);
    if (sms <= 0) sms = 152;
    int grid = sms * 2;   // 2 CTAs per SM, nh pairs co-resident
    cudaFuncSetAttribute(lstm_kernel, cudaFuncAttributeMaxDynamicSharedMemorySize, SMEM_BYTES);
    lstm_kernel<<<grid, NTHREADS, SMEM_BYTES>>>(
        (const float*)d_in[0], (const float*)d_in[1], (const float*)d_in[2], (float*)d_out);
}